// round 9
// baseline (speedup 1.0000x reference)
#include <cuda_runtime.h>
#include <cuda_bf16.h>
#include <cstddef>

// Problem constants
#define Bn  4
#define Ln  1024
#define En  256
#define Hn  8
#define DHn 32

// ---------------- scratch (device globals; no allocation allowed) -----------
__device__ float g_q[Bn * Ln * En];        // Q pre-scaled by 1/16, layout [b][n][h*32+d]
__device__ float g_k[Bn * Hn * Ln * DHn];  // K head-major [b][h][m][d]
__device__ float g_v[Bn * Hn * Ln * DHn];  // V head-major [b][h][m][d]
__device__ float g_attn[Bn * Ln * En];     // attention output [b][n][h*32+d]
__device__ int   g_adj_is_byte;            // 1 = adjacency stored as 1-byte elems

// ---------------- adjacency dtype detection ---------------------------------
// If adj is uint8: adj[n*L+n] == 1 for every n (diagonal forced true).
// If adj is int32/float32 (values 0/1 or 0.0/1.0): the byte at offset n*1025
// lands mid-element for n % 4 != 0 and is always 0 (n=1 already fails).
// All probed offsets are < 1 MB, within the smallest possible buffer (4 MB).
__global__ void detect_adj_kernel(const unsigned char* __restrict__ adj)
{
    int ok = 1;
    for (int n = 0; n < Ln; n++) {
        if (adj[(size_t)n * Ln + n] != 1) { ok = 0; break; }
    }
    g_adj_is_byte = ok;
}

// ---------------- SGEMM: C[4096x256] = A[4096x256] @ W[256x256]^T + bias ----
// mode 0: C[r*256+c] = v * (1/16)                       (Q, pre-scaled)
// mode 1: head-major scatter [b][h][l][d]               (K / V)
// mode 2: C[r*256+c] = v                                (plain, output proj)
__global__ void __launch_bounds__(256)
gemm_kernel(const float* __restrict__ A, const float* __restrict__ W,
            const float* __restrict__ bias, float* __restrict__ C, int mode)
{
    __shared__ __align__(16) float As[8][128];
    __shared__ __align__(16) float Bs[8][128];

    const int tid  = threadIdx.x;
    const int row0 = blockIdx.y * 128;
    const int col0 = blockIdx.x * 128;
    const int ty = tid >> 4, tx = tid & 15;      // 16x16 thread grid, 8x8 per thread
    const int lr = tid >> 1, lk = (tid & 1) * 4; // loader coords

    float acc[8][8];
#pragma unroll
    for (int i = 0; i < 8; i++)
#pragma unroll
        for (int j = 0; j < 8; j++) acc[i][j] = 0.f;

    const float* Ap = A + (size_t)(row0 + lr) * 256 + lk;
    const float* Wp = W + (size_t)(col0 + lr) * 256 + lk;

    for (int k0 = 0; k0 < 256; k0 += 8) {
        float4 a4 = *(const float4*)(Ap + k0);
        float4 b4 = *(const float4*)(Wp + k0);
        __syncthreads();
        As[lk + 0][lr] = a4.x; As[lk + 1][lr] = a4.y;
        As[lk + 2][lr] = a4.z; As[lk + 3][lr] = a4.w;
        Bs[lk + 0][lr] = b4.x; Bs[lk + 1][lr] = b4.y;
        Bs[lk + 2][lr] = b4.z; Bs[lk + 3][lr] = b4.w;
        __syncthreads();
#pragma unroll
        for (int kk = 0; kk < 8; kk++) {
            float ar[8], br[8];
            *(float4*)(ar)     = *(const float4*)&As[kk][ty * 8];
            *(float4*)(ar + 4) = *(const float4*)&As[kk][ty * 8 + 4];
            *(float4*)(br)     = *(const float4*)&Bs[kk][tx * 8];
            *(float4*)(br + 4) = *(const float4*)&Bs[kk][tx * 8 + 4];
#pragma unroll
            for (int i = 0; i < 8; i++)
#pragma unroll
                for (int j = 0; j < 8; j++)
                    acc[i][j] = fmaf(ar[i], br[j], acc[i][j]);
        }
    }

#pragma unroll
    for (int i = 0; i < 8; i++) {
        int r = row0 + ty * 8 + i;
#pragma unroll
        for (int j = 0; j < 8; j++) {
            int c = col0 + tx * 8 + j;
            float v = acc[i][j] + bias[c];
            if (mode == 0) {
                C[(size_t)r * 256 + c] = v * 0.0625f;   // 1/sqrt(256)
            } else if (mode == 1) {
                // r = b*1024 + l ; c = h*32 + d  ->  [b][h][l][d]
                int idx = (((r >> 10) * Hn + (c >> 5)) * Ln + (r & 1023)) * DHn + (c & 31);
                C[idx] = v;
            } else {
                C[(size_t)r * 256 + c] = v;
            }
        }
    }
}

// ---------------- fused sparse attention ------------------------------------
// CTA = (b, n): one query row, all 8 heads. 256 threads = 8 warps, warp = head.
// Adjacency row is compacted once into a shared neighbor list; each warp does
// warp-cooperative dots (lane = d), warp-parallel softmax, then p.V accumulate.
__global__ void __launch_bounds__(256)
attn_kernel(const void* __restrict__ AdjRaw, const float* __restrict__ Eg,
            float* __restrict__ Ob)
{
    __shared__ float q_s[En];
    __shared__ int   m_list[Ln];
    __shared__ float sc[Hn][Ln];     // scores -> probs, 32 KB
    __shared__ int   m_cnt;

    const int n   = blockIdx.x;
    const int b   = blockIdx.y;
    const int tid = threadIdx.x;
    const int w    = tid >> 5;       // head
    const int lane = tid & 31;       // d
    const int isbyte = g_adj_is_byte;

    // Q row (already scaled by 1/16)
    q_s[tid] = g_q[(size_t)(b * Ln + n) * En + tid];
    if (tid == 0) m_cnt = 0;
    __syncthreads();

    // ---- compact the adjacency row into m_list (unordered; order only
    //      perturbs fp summation order, within tolerance) ----
    const unsigned char* arow8  = (const unsigned char*)AdjRaw + (size_t)(b * Ln + n) * Ln;
    const unsigned int*  arow32 = (const unsigned int*) AdjRaw + (size_t)(b * Ln + n) * Ln;
#pragma unroll
    for (int base = 0; base < Ln; base += 256) {
        int m = base + tid;
        bool valid = isbyte ? (arow8[m] != 0) : (arow32[m] != 0u);
        unsigned bal = __ballot_sync(0xffffffffu, valid);
        int pos = 0;
        if (lane == 0 && bal) pos = atomicAdd(&m_cnt, __popc(bal));
        pos = __shfl_sync(0xffffffffu, pos, 0);
        if (valid) m_list[pos + __popc(bal & ((1u << lane) - 1))] = m;
    }
    __syncthreads();
    const int cnt = m_cnt;   // >= 1 (diagonal always set)

    const float  qd   = q_s[w * DHn + lane];
    const float* Kh   = g_k + (size_t)(b * Hn + w) * Ln * DHn;
    const float* Vh   = g_v + (size_t)(b * Hn + w) * Ln * DHn;
    const float* Erow = Eg + (size_t)(b * Ln + n) * Ln * DHn;

    // ---- scores: s = (Q/16) . (K_m + E_nm), warp-cooperative (lane = d) ----
    int i = 0;
    for (; i + 1 < cnt; i += 2) {
        int m0 = m_list[i], m1 = m_list[i + 1];
        float s0 = qd * (Kh[(size_t)m0 * DHn + lane] + Erow[(size_t)m0 * DHn + lane]);
        float s1 = qd * (Kh[(size_t)m1 * DHn + lane] + Erow[(size_t)m1 * DHn + lane]);
#pragma unroll
        for (int off = 16; off > 0; off >>= 1) {
            s0 += __shfl_xor_sync(0xffffffffu, s0, off);
            s1 += __shfl_xor_sync(0xffffffffu, s1, off);
        }
        if (lane == 0) { sc[w][i] = s0; sc[w][i + 1] = s1; }
    }
    for (; i < cnt; i++) {
        int m0 = m_list[i];
        float s0 = qd * (Kh[(size_t)m0 * DHn + lane] + Erow[(size_t)m0 * DHn + lane]);
#pragma unroll
        for (int off = 16; off > 0; off >>= 1)
            s0 += __shfl_xor_sync(0xffffffffu, s0, off);
        if (lane == 0) sc[w][i] = s0;
    }
    __syncwarp();

    // ---- softmax over the neighbor list (warp-parallel) ----
    float mx = -1e30f;
    for (int j = lane; j < cnt; j += 32) mx = fmaxf(mx, sc[w][j]);
#pragma unroll
    for (int off = 16; off > 0; off >>= 1)
        mx = fmaxf(mx, __shfl_xor_sync(0xffffffffu, mx, off));

    float sum = 0.f;
    for (int j = lane; j < cnt; j += 32) {
        float p = __expf(sc[w][j] - mx);
        sc[w][j] = p;
        sum += p;
    }
#pragma unroll
    for (int off = 16; off > 0; off >>= 1)
        sum += __shfl_xor_sync(0xffffffffu, sum, off);
    const float inv = (sum > 0.f) ? (1.f / sum) : 0.f;
    __syncwarp();

    // ---- out = sum_m p_m * V[m], lane = d ----
    float acc = 0.f;
    int j = 0;
    for (; j + 3 < cnt; j += 4) {
        int ma = m_list[j],     mb = m_list[j + 1];
        int mc = m_list[j + 2], md = m_list[j + 3];
        float pa = sc[w][j],     pb = sc[w][j + 1];
        float pc = sc[w][j + 2], pd = sc[w][j + 3];
        float va = Vh[(size_t)ma * DHn + lane];
        float vb = Vh[(size_t)mb * DHn + lane];
        float vc = Vh[(size_t)mc * DHn + lane];
        float vd = Vh[(size_t)md * DHn + lane];
        acc = fmaf(pa, va, acc);
        acc = fmaf(pb, vb, acc);
        acc = fmaf(pc, vc, acc);
        acc = fmaf(pd, vd, acc);
    }
    for (; j < cnt; j++)
        acc = fmaf(sc[w][j], Vh[(size_t)m_list[j] * DHn + lane], acc);

    Ob[(size_t)(b * Ln + n) * En + w * DHn + lane] = acc * inv;
}

// ---------------- launch ----------------------------------------------------
extern "C" void kernel_launch(void* const* d_in, const int* in_sizes, int n_in,
                              void* d_out, int out_size)
{
    const float* nf  = (const float*)d_in[0];
    const void*  adj = d_in[1];
    const float* eg  = (const float*)d_in[2];
    const float* Wq = (const float*)d_in[3];
    const float* bq = (const float*)d_in[4];
    const float* Wk = (const float*)d_in[5];
    const float* bk = (const float*)d_in[6];
    const float* Wv = (const float*)d_in[7];
    const float* bv = (const float*)d_in[8];
    const float* Wo = (const float*)d_in[9];
    const float* bo = (const float*)d_in[10];
    float* out = (float*)d_out;

    float *q, *k, *v, *at;
    cudaGetSymbolAddress((void**)&q,  g_q);
    cudaGetSymbolAddress((void**)&k,  g_k);
    cudaGetSymbolAddress((void**)&v,  g_v);
    cudaGetSymbolAddress((void**)&at, g_attn);

    detect_adj_kernel<<<1, 1>>>((const unsigned char*)adj);

    dim3 ggrid(En / 128, (Bn * Ln) / 128);   // (2, 32)
    gemm_kernel<<<ggrid, 256>>>(nf, Wq, bq, q, 0);
    gemm_kernel<<<ggrid, 256>>>(nf, Wk, bk, k, 1);
    gemm_kernel<<<ggrid, 256>>>(nf, Wv, bv, v, 1);

    dim3 agrid(Ln, Bn);                      // (1024, 4)
    attn_kernel<<<agrid, 256>>>(adj, eg, at);

    gemm_kernel<<<ggrid, 256>>>(at, Wo, bo, out, 2);
}

// round 10
// speedup vs baseline: 1.9954x; 1.9954x over previous
#include <cuda_runtime.h>
#include <cuda_bf16.h>
#include <cstddef>

// Problem constants
#define Bn  4
#define Ln  1024
#define En  256
#define Hn  8
#define DHn 32
#define LDST 68   // smem row stride (floats): 16B-aligned, conflict-mitigating

// ---------------- scratch (device globals; no allocation allowed) -----------
__device__ float g_q[Bn * Ln * En];        // Q pre-scaled by 1/16, [b][n][h*32+d]
__device__ float g_k[Bn * Hn * Ln * DHn];  // K head-major [b][h][m][d]
__device__ float g_v[Bn * Hn * Ln * DHn];  // V head-major [b][h][m][d]
__device__ float g_attn[Bn * Ln * En];     // attention output [b][n][h*32+d]
__device__ int   g_adj_is_byte;            // 1 = adjacency stored as 1-byte elems

// ---------------- adjacency dtype detection ---------------------------------
// uint8 layout: byte at n*L+n is 1 for every n (diagonal forced true).
// int32/float32 layout: byte at offset n*1025 lands mid-element for n%4!=0 -> 0.
__global__ void detect_adj_kernel(const unsigned char* __restrict__ adj)
{
    int ok = 1;
    for (int n = 0; n < Ln; n++) {
        if (adj[(size_t)n * Ln + n] != 1) { ok = 0; break; }
    }
    g_adj_is_byte = ok;
}

// ---------------- shared 64x64 SGEMM mainloop --------------------------------
// Computes acc[4][4] = A[row0+ty*4+i][:] . W[col0+tx*4+j][:]  (K = 256)
__device__ __forceinline__ void gemm64_body(const float* __restrict__ A,
                                            const float* __restrict__ W,
                                            int row0, int col0,
                                            float (&acc)[4][4],
                                            float* As, float* Bs)
{
    const int tid  = threadIdx.x;
    const int ty   = tid >> 4, tx = tid & 15;
    const int lrow = tid >> 2, lks = (tid & 3) * 4;

    const float* Ap = A + (size_t)(row0 + lrow) * 256 + lks;
    const float* Wp = W + (size_t)(col0 + lrow) * 256 + lks;

    for (int kc = 0; kc < 256; kc += 16) {
        float4 a4 = *(const float4*)(Ap + kc);
        float4 b4 = *(const float4*)(Wp + kc);
        __syncthreads();
        As[(lks + 0) * LDST + lrow] = a4.x;
        As[(lks + 1) * LDST + lrow] = a4.y;
        As[(lks + 2) * LDST + lrow] = a4.z;
        As[(lks + 3) * LDST + lrow] = a4.w;
        Bs[(lks + 0) * LDST + lrow] = b4.x;
        Bs[(lks + 1) * LDST + lrow] = b4.y;
        Bs[(lks + 2) * LDST + lrow] = b4.z;
        Bs[(lks + 3) * LDST + lrow] = b4.w;
        __syncthreads();
#pragma unroll
        for (int k = 0; k < 16; k++) {
            float4 av = *(const float4*)&As[k * LDST + ty * 4];
            float4 bv = *(const float4*)&Bs[k * LDST + tx * 4];
            acc[0][0] = fmaf(av.x, bv.x, acc[0][0]);
            acc[0][1] = fmaf(av.x, bv.y, acc[0][1]);
            acc[0][2] = fmaf(av.x, bv.z, acc[0][2]);
            acc[0][3] = fmaf(av.x, bv.w, acc[0][3]);
            acc[1][0] = fmaf(av.y, bv.x, acc[1][0]);
            acc[1][1] = fmaf(av.y, bv.y, acc[1][1]);
            acc[1][2] = fmaf(av.y, bv.z, acc[1][2]);
            acc[1][3] = fmaf(av.y, bv.w, acc[1][3]);
            acc[2][0] = fmaf(av.z, bv.x, acc[2][0]);
            acc[2][1] = fmaf(av.z, bv.y, acc[2][1]);
            acc[2][2] = fmaf(av.z, bv.z, acc[2][2]);
            acc[2][3] = fmaf(av.z, bv.w, acc[2][3]);
            acc[3][0] = fmaf(av.w, bv.x, acc[3][0]);
            acc[3][1] = fmaf(av.w, bv.y, acc[3][1]);
            acc[3][2] = fmaf(av.w, bv.z, acc[3][2]);
            acc[3][3] = fmaf(av.w, bv.w, acc[3][3]);
        }
    }
}

// ---------------- fused QKV projection ---------------------------------------
// grid (12, 64): bx selects (matrix, 64-col slab); by selects 64-row slab.
__global__ void __launch_bounds__(256)
qkv_gemm_kernel(const float* __restrict__ A,
                const float* __restrict__ Wq, const float* __restrict__ bq,
                const float* __restrict__ Wk, const float* __restrict__ bk,
                const float* __restrict__ Wv, const float* __restrict__ bv)
{
    __shared__ __align__(16) float As[16 * LDST];
    __shared__ __align__(16) float Bs[16 * LDST];

    const int wsel = blockIdx.x >> 2;            // 0=Q 1=K 2=V
    const int col0 = (blockIdx.x & 3) * 64;      // col within selected W
    const int row0 = blockIdx.y * 64;

    const float* W    = (wsel == 0) ? Wq : (wsel == 1) ? Wk : Wv;
    const float* bias = (wsel == 0) ? bq : (wsel == 1) ? bk : bv;

    float acc[4][4];
#pragma unroll
    for (int i = 0; i < 4; i++)
#pragma unroll
        for (int j = 0; j < 4; j++) acc[i][j] = 0.f;

    gemm64_body(A, W, row0, col0, acc, As, Bs);

    const int ty = threadIdx.x >> 4, tx = threadIdx.x & 15;
#pragma unroll
    for (int i = 0; i < 4; i++) {
        int r = row0 + ty * 4 + i;
#pragma unroll
        for (int j = 0; j < 4; j++) {
            int c = col0 + tx * 4 + j;
            float v = acc[i][j] + bias[c];
            if (wsel == 0) {
                g_q[(size_t)r * 256 + c] = v * 0.0625f;  // pre-scale 1/sqrt(256)
            } else {
                // r = b*1024 + l ; c = h*32 + d  ->  [b][h][l][d]
                int idx = (((r >> 10) * Hn + (c >> 5)) * Ln + (r & 1023)) * DHn + (c & 31);
                if (wsel == 1) g_k[idx] = v; else g_v[idx] = v;
            }
        }
    }
}

// ---------------- output projection ------------------------------------------
__global__ void __launch_bounds__(256)
out_gemm_kernel(const float* __restrict__ A, const float* __restrict__ W,
                const float* __restrict__ bias, float* __restrict__ C)
{
    __shared__ __align__(16) float As[16 * LDST];
    __shared__ __align__(16) float Bs[16 * LDST];

    const int col0 = blockIdx.x * 64;
    const int row0 = blockIdx.y * 64;

    float acc[4][4];
#pragma unroll
    for (int i = 0; i < 4; i++)
#pragma unroll
        for (int j = 0; j < 4; j++) acc[i][j] = 0.f;

    gemm64_body(A, W, row0, col0, acc, As, Bs);

    const int ty = threadIdx.x >> 4, tx = threadIdx.x & 15;
#pragma unroll
    for (int i = 0; i < 4; i++) {
        int r = row0 + ty * 4 + i;
#pragma unroll
        for (int j = 0; j < 4; j++) {
            int c = col0 + tx * 4 + j;
            C[(size_t)r * 256 + c] = acc[i][j] + bias[c];
        }
    }
}

// ---------------- fused sparse attention ------------------------------------
// CTA = (b, n): one query row, all 8 heads. 256 threads = 8 warps, warp = head.
// Score + PV phases use 8 lanes per neighbor, 4 neighbors per warp-iteration,
// float4 loads throughout.
__global__ void __launch_bounds__(256)
attn_kernel(const void* __restrict__ AdjRaw, const float* __restrict__ Eg,
            float* __restrict__ Ob)
{
    __shared__ float q_s[En];
    __shared__ int   m_list[Ln];
    __shared__ float sc[Hn][Ln];     // scores -> unnormalized probs
    __shared__ int   m_cnt;

    const int n    = blockIdx.x;
    const int b    = blockIdx.y;
    const int tid  = threadIdx.x;
    const int w    = tid >> 5;       // head
    const int lane = tid & 31;
    const int g    = lane >> 3;      // neighbor sub-group 0..3
    const int sub  = lane & 7;       // d-quad index 0..7 (d = sub*4..sub*4+3)
    const int isbyte = g_adj_is_byte;

    q_s[tid] = g_q[(size_t)(b * Ln + n) * En + tid];
    if (tid == 0) m_cnt = 0;
    __syncthreads();

    // ---- compact the adjacency row into m_list ----
    const unsigned char* arow8  = (const unsigned char*)AdjRaw + (size_t)(b * Ln + n) * Ln;
    const unsigned int*  arow32 = (const unsigned int*) AdjRaw + (size_t)(b * Ln + n) * Ln;
#pragma unroll
    for (int base = 0; base < Ln; base += 256) {
        int m = base + tid;
        bool valid = isbyte ? (arow8[m] != 0) : (arow32[m] != 0u);
        unsigned bal = __ballot_sync(0xffffffffu, valid);
        int pos = 0;
        if (lane == 0 && bal) pos = atomicAdd(&m_cnt, __popc(bal));
        pos = __shfl_sync(0xffffffffu, pos, 0);
        if (valid) m_list[pos + __popc(bal & ((1u << lane) - 1))] = m;
    }
    __syncthreads();
    const int cnt = m_cnt;   // >= 1 (diagonal always set)

    const float* Kh   = g_k + (size_t)(b * Hn + w) * Ln * DHn;
    const float* Vh   = g_v + (size_t)(b * Hn + w) * Ln * DHn;
    const float* Erow = Eg + (size_t)(b * Ln + n) * Ln * DHn;

    // Per-lane Q quad: head w, dims sub*4..sub*4+3 (already scaled by 1/16)
    const float4 q4 = *(const float4*)&q_s[w * DHn + sub * 4];

    // ---- scores: s = Q . (K_m + E_nm); 8 lanes per neighbor, 4 at a time ----
    for (int i = 0; i < cnt; i += 4) {
        int jj = i + g;
        int m  = m_list[(jj < cnt) ? jj : 0];
        const float4 k4 = *(const float4*)(Kh + (size_t)m * DHn + sub * 4);
        const float4 e4 = *(const float4*)(Erow + (size_t)m * DHn + sub * 4);
        float s;
        s = q4.x * (k4.x + e4.x);
        s = fmaf(q4.y, k4.y + e4.y, s);
        s = fmaf(q4.z, k4.z + e4.z, s);
        s = fmaf(q4.w, k4.w + e4.w, s);
        s += __shfl_xor_sync(0xffffffffu, s, 1);
        s += __shfl_xor_sync(0xffffffffu, s, 2);
        s += __shfl_xor_sync(0xffffffffu, s, 4);
        if (sub == 0 && jj < cnt) sc[w][jj] = s;
    }
    __syncwarp();

    // ---- softmax over the neighbor list (warp-parallel) ----
    float mx = -1e30f;
    for (int j = lane; j < cnt; j += 32) mx = fmaxf(mx, sc[w][j]);
#pragma unroll
    for (int off = 16; off > 0; off >>= 1)
        mx = fmaxf(mx, __shfl_xor_sync(0xffffffffu, mx, off));

    float sum = 0.f;
    for (int j = lane; j < cnt; j += 32) {
        float p = __expf(sc[w][j] - mx);
        sc[w][j] = p;
        sum += p;
    }
#pragma unroll
    for (int off = 16; off > 0; off >>= 1)
        sum += __shfl_xor_sync(0xffffffffu, sum, off);
    const float inv = 1.f / sum;
    __syncwarp();

    // ---- out = sum_m p_m * V[m]; 8 lanes per neighbor, 4 at a time ----
    float4 acc = make_float4(0.f, 0.f, 0.f, 0.f);
    for (int j = 0; j < cnt; j += 4) {
        int jj = j + g;
        bool ok = (jj < cnt);
        int m   = m_list[ok ? jj : 0];
        float p = ok ? sc[w][jj] : 0.f;
        const float4 v4 = *(const float4*)(Vh + (size_t)m * DHn + sub * 4);
        acc.x = fmaf(p, v4.x, acc.x);
        acc.y = fmaf(p, v4.y, acc.y);
        acc.z = fmaf(p, v4.z, acc.z);
        acc.w = fmaf(p, v4.w, acc.w);
    }
    // combine the 4 neighbor-groups (lanes differing in bits 3,4)
#pragma unroll
    for (int off = 8; off <= 16; off <<= 1) {
        acc.x += __shfl_xor_sync(0xffffffffu, acc.x, off);
        acc.y += __shfl_xor_sync(0xffffffffu, acc.y, off);
        acc.z += __shfl_xor_sync(0xffffffffu, acc.z, off);
        acc.w += __shfl_xor_sync(0xffffffffu, acc.w, off);
    }
    if (g == 0) {
        float4 o = make_float4(acc.x * inv, acc.y * inv, acc.z * inv, acc.w * inv);
        *(float4*)(Ob + (size_t)(b * Ln + n) * En + w * DHn + sub * 4) = o;
    }
}

// ---------------- launch ----------------------------------------------------
extern "C" void kernel_launch(void* const* d_in, const int* in_sizes, int n_in,
                              void* d_out, int out_size)
{
    const float* nf  = (const float*)d_in[0];
    const void*  adj = d_in[1];
    const float* eg  = (const float*)d_in[2];
    const float* Wq = (const float*)d_in[3];
    const float* bq = (const float*)d_in[4];
    const float* Wk = (const float*)d_in[5];
    const float* bk = (const float*)d_in[6];
    const float* Wv = (const float*)d_in[7];
    const float* bv = (const float*)d_in[8];
    const float* Wo = (const float*)d_in[9];
    const float* bo = (const float*)d_in[10];
    float* out = (float*)d_out;

    float *at;
    cudaGetSymbolAddress((void**)&at, g_attn);

    detect_adj_kernel<<<1, 1>>>((const unsigned char*)adj);

    dim3 qkv_grid(12, (Bn * Ln) / 64);   // (12, 64) = 768 CTAs
    qkv_gemm_kernel<<<qkv_grid, 256>>>(nf, Wq, bq, Wk, bk, Wv, bv);

    dim3 agrid(Ln, Bn);                  // (1024, 4)
    attn_kernel<<<agrid, 256>>>(adj, eg, at);

    dim3 ogrid(En / 64, (Bn * Ln) / 64); // (4, 64) = 256 CTAs
    out_gemm_kernel<<<ogrid, 256>>>(at, Wo, bo, out);
}

// round 11
// speedup vs baseline: 2.1442x; 1.0746x over previous
#include <cuda_runtime.h>
#include <cuda_bf16.h>
#include <cstddef>

// Problem constants
#define Bn  4
#define Ln  1024
#define En  256
#define Hn  8
#define DHn 32
#define LDST 68   // smem row stride (floats): 16B-aligned, conflict-mitigating

// ---------------- scratch (device globals; no allocation allowed) -----------
__device__ float g_q[Bn * Ln * En];        // Q pre-scaled by 1/16, [b][n][h*32+d]
__device__ float g_k[Bn * Hn * Ln * DHn];  // K head-major [b][h][m][d]
__device__ float g_v[Bn * Hn * Ln * DHn];  // V head-major [b][h][m][d]
__device__ float g_attn[Bn * Ln * En];     // attention output [b][n][h*32+d]
__device__ int   g_adj_is_byte;            // 1 = adjacency stored as 1-byte elems

// ---------------- adjacency dtype detection (parallel, ~1us) -----------------
// uint8 layout: byte at n*L+n is 1 for every n (diagonal forced true).
// int32/float32 layout: byte at offset n*1025 lands mid-element for n%4!=0 -> 0.
__global__ void __launch_bounds__(1024)
detect_adj_kernel(const unsigned char* __restrict__ adj)
{
    __shared__ int ok;
    if (threadIdx.x == 0) ok = 1;
    __syncthreads();
    if (adj[(size_t)threadIdx.x * Ln + threadIdx.x] != 1) ok = 0;  // benign race
    __syncthreads();
    if (threadIdx.x == 0) g_adj_is_byte = ok;
}

// ---------------- shared 64x64 SGEMM mainloop (prefetched) -------------------
// acc[4][4] = A[row0+ty*4+i][:] . W[col0+tx*4+j][:]  (K = 256)
__device__ __forceinline__ void gemm64_body(const float* __restrict__ A,
                                            const float* __restrict__ W,
                                            int row0, int col0,
                                            float (&acc)[4][4],
                                            float* As, float* Bs)
{
    const int tid  = threadIdx.x;
    const int ty   = tid >> 4, tx = tid & 15;
    const int lrow = tid >> 2, lks = (tid & 3) * 4;

    const float* Ap = A + (size_t)(row0 + lrow) * 256 + lks;
    const float* Wp = W + (size_t)(col0 + lrow) * 256 + lks;

    // prefetch chunk 0
    float4 a4 = *(const float4*)(Ap);
    float4 b4 = *(const float4*)(Wp);

#pragma unroll 1
    for (int kc = 0; kc < 256; kc += 16) {
        __syncthreads();
        As[(lks + 0) * LDST + lrow] = a4.x;
        As[(lks + 1) * LDST + lrow] = a4.y;
        As[(lks + 2) * LDST + lrow] = a4.z;
        As[(lks + 3) * LDST + lrow] = a4.w;
        Bs[(lks + 0) * LDST + lrow] = b4.x;
        Bs[(lks + 1) * LDST + lrow] = b4.y;
        Bs[(lks + 2) * LDST + lrow] = b4.z;
        Bs[(lks + 3) * LDST + lrow] = b4.w;
        __syncthreads();
        // issue next chunk's loads BEFORE the compute block (latency hidden
        // behind 256 FMAs per thread)
        if (kc + 16 < 256) {
            a4 = *(const float4*)(Ap + kc + 16);
            b4 = *(const float4*)(Wp + kc + 16);
        }
#pragma unroll
        for (int k = 0; k < 16; k++) {
            float4 av = *(const float4*)&As[k * LDST + ty * 4];
            float4 bv = *(const float4*)&Bs[k * LDST + tx * 4];
            acc[0][0] = fmaf(av.x, bv.x, acc[0][0]);
            acc[0][1] = fmaf(av.x, bv.y, acc[0][1]);
            acc[0][2] = fmaf(av.x, bv.z, acc[0][2]);
            acc[0][3] = fmaf(av.x, bv.w, acc[0][3]);
            acc[1][0] = fmaf(av.y, bv.x, acc[1][0]);
            acc[1][1] = fmaf(av.y, bv.y, acc[1][1]);
            acc[1][2] = fmaf(av.y, bv.z, acc[1][2]);
            acc[1][3] = fmaf(av.y, bv.w, acc[1][3]);
            acc[2][0] = fmaf(av.z, bv.x, acc[2][0]);
            acc[2][1] = fmaf(av.z, bv.y, acc[2][1]);
            acc[2][2] = fmaf(av.z, bv.z, acc[2][2]);
            acc[2][3] = fmaf(av.z, bv.w, acc[2][3]);
            acc[3][0] = fmaf(av.w, bv.x, acc[3][0]);
            acc[3][1] = fmaf(av.w, bv.y, acc[3][1]);
            acc[3][2] = fmaf(av.w, bv.z, acc[3][2]);
            acc[3][3] = fmaf(av.w, bv.w, acc[3][3]);
        }
    }
}

// ---------------- fused QKV projection ---------------------------------------
// grid (12, 64): bx selects (matrix, 64-col slab); by selects 64-row slab.
__global__ void __launch_bounds__(256)
qkv_gemm_kernel(const float* __restrict__ A,
                const float* __restrict__ Wq, const float* __restrict__ bq,
                const float* __restrict__ Wk, const float* __restrict__ bk,
                const float* __restrict__ Wv, const float* __restrict__ bv)
{
    __shared__ __align__(16) float As[16 * LDST];
    __shared__ __align__(16) float Bs[16 * LDST];

    const int wsel = blockIdx.x >> 2;            // 0=Q 1=K 2=V
    const int col0 = (blockIdx.x & 3) * 64;      // col within selected W
    const int row0 = blockIdx.y * 64;

    const float* W    = (wsel == 0) ? Wq : (wsel == 1) ? Wk : Wv;
    const float* bias = (wsel == 0) ? bq : (wsel == 1) ? bk : bv;

    float acc[4][4];
#pragma unroll
    for (int i = 0; i < 4; i++)
#pragma unroll
        for (int j = 0; j < 4; j++) acc[i][j] = 0.f;

    gemm64_body(A, W, row0, col0, acc, As, Bs);

    const int ty = threadIdx.x >> 4, tx = threadIdx.x & 15;
#pragma unroll
    for (int i = 0; i < 4; i++) {
        int r = row0 + ty * 4 + i;
#pragma unroll
        for (int j = 0; j < 4; j++) {
            int c = col0 + tx * 4 + j;
            float v = acc[i][j] + bias[c];
            if (wsel == 0) {
                g_q[(size_t)r * 256 + c] = v * 0.0625f;  // pre-scale 1/sqrt(256)
            } else {
                // r = b*1024 + l ; c = h*32 + d  ->  [b][h][l][d]
                int idx = (((r >> 10) * Hn + (c >> 5)) * Ln + (r & 1023)) * DHn + (c & 31);
                if (wsel == 1) g_k[idx] = v; else g_v[idx] = v;
            }
        }
    }
}

// ---------------- output projection ------------------------------------------
__global__ void __launch_bounds__(256)
out_gemm_kernel(const float* __restrict__ A, const float* __restrict__ W,
                const float* __restrict__ bias, float* __restrict__ C)
{
    __shared__ __align__(16) float As[16 * LDST];
    __shared__ __align__(16) float Bs[16 * LDST];

    const int col0 = blockIdx.x * 64;
    const int row0 = blockIdx.y * 64;

    float acc[4][4];
#pragma unroll
    for (int i = 0; i < 4; i++)
#pragma unroll
        for (int j = 0; j < 4; j++) acc[i][j] = 0.f;

    gemm64_body(A, W, row0, col0, acc, As, Bs);

    const int ty = threadIdx.x >> 4, tx = threadIdx.x & 15;
#pragma unroll
    for (int i = 0; i < 4; i++) {
        int r = row0 + ty * 4 + i;
#pragma unroll
        for (int j = 0; j < 4; j++) {
            int c = col0 + tx * 4 + j;
            C[(size_t)r * 256 + c] = acc[i][j] + bias[c];
        }
    }
}

// ---------------- fused sparse attention ------------------------------------
// CTA = (b, n): one query row, all 8 heads. 256 threads = 8 warps, warp = head.
// Score + PV phases: 8 lanes per neighbor, 8 neighbors per warp-iteration
// (2-deep unroll -> 4 independent LDG.128 in flight per lane).
__global__ void __launch_bounds__(256)
attn_kernel(const void* __restrict__ AdjRaw, const float* __restrict__ Eg,
            float* __restrict__ Ob)
{
    __shared__ float q_s[En];
    __shared__ int   m_list[Ln];
    __shared__ float sc[Hn][Ln];     // scores -> unnormalized probs
    __shared__ int   m_cnt;

    const int n    = blockIdx.x;
    const int b    = blockIdx.y;
    const int tid  = threadIdx.x;
    const int w    = tid >> 5;       // head
    const int lane = tid & 31;
    const int g    = lane >> 3;      // neighbor sub-group 0..3
    const int sub  = lane & 7;       // d-quad index (d = sub*4..sub*4+3)
    const int isbyte = g_adj_is_byte;

    q_s[tid] = g_q[(size_t)(b * Ln + n) * En + tid];
    if (tid == 0) m_cnt = 0;
    __syncthreads();

    // ---- compact the adjacency row into m_list ----
    const unsigned char* arow8  = (const unsigned char*)AdjRaw + (size_t)(b * Ln + n) * Ln;
    const unsigned int*  arow32 = (const unsigned int*) AdjRaw + (size_t)(b * Ln + n) * Ln;
#pragma unroll
    for (int base = 0; base < Ln; base += 256) {
        int m = base + tid;
        bool valid = isbyte ? (arow8[m] != 0) : (arow32[m] != 0u);
        unsigned bal = __ballot_sync(0xffffffffu, valid);
        int pos = 0;
        if (lane == 0 && bal) pos = atomicAdd(&m_cnt, __popc(bal));
        pos = __shfl_sync(0xffffffffu, pos, 0);
        if (valid) m_list[pos + __popc(bal & ((1u << lane) - 1))] = m;
    }
    __syncthreads();
    const int cnt = m_cnt;   // >= 1 (diagonal always set)

    const float* Kh   = g_k + (size_t)(b * Hn + w) * Ln * DHn;
    const float* Vh   = g_v + (size_t)(b * Hn + w) * Ln * DHn;
    const float* Erow = Eg + (size_t)(b * Ln + n) * Ln * DHn;

    // Per-lane Q quad: head w, dims sub*4..sub*4+3 (already scaled by 1/16)
    const float4 q4 = *(const float4*)&q_s[w * DHn + sub * 4];

    // ---- scores: s = Q . (K_m + E_nm); 8 neighbors per iteration ----
    for (int i = 0; i < cnt; i += 8) {
        const int j0 = i + g, j1 = i + 4 + g;
        const int m0 = m_list[(j0 < cnt) ? j0 : 0];
        const int m1 = m_list[(j1 < cnt) ? j1 : 0];
        const float4 k0 = *(const float4*)(Kh   + (size_t)m0 * DHn + sub * 4);
        const float4 e0 = *(const float4*)(Erow + (size_t)m0 * DHn + sub * 4);
        const float4 k1 = *(const float4*)(Kh   + (size_t)m1 * DHn + sub * 4);
        const float4 e1 = *(const float4*)(Erow + (size_t)m1 * DHn + sub * 4);
        float s0, s1;
        s0 = q4.x * (k0.x + e0.x);
        s1 = q4.x * (k1.x + e1.x);
        s0 = fmaf(q4.y, k0.y + e0.y, s0);
        s1 = fmaf(q4.y, k1.y + e1.y, s1);
        s0 = fmaf(q4.z, k0.z + e0.z, s0);
        s1 = fmaf(q4.z, k1.z + e1.z, s1);
        s0 = fmaf(q4.w, k0.w + e0.w, s0);
        s1 = fmaf(q4.w, k1.w + e1.w, s1);
        s0 += __shfl_xor_sync(0xffffffffu, s0, 1);
        s1 += __shfl_xor_sync(0xffffffffu, s1, 1);
        s0 += __shfl_xor_sync(0xffffffffu, s0, 2);
        s1 += __shfl_xor_sync(0xffffffffu, s1, 2);
        s0 += __shfl_xor_sync(0xffffffffu, s0, 4);
        s1 += __shfl_xor_sync(0xffffffffu, s1, 4);
        if (sub == 0) {
            if (j0 < cnt) sc[w][j0] = s0;
            if (j1 < cnt) sc[w][j1] = s1;
        }
    }
    __syncwarp();

    // ---- softmax over the neighbor list (warp-parallel) ----
    float mx = -1e30f;
    for (int j = lane; j < cnt; j += 32) mx = fmaxf(mx, sc[w][j]);
#pragma unroll
    for (int off = 16; off > 0; off >>= 1)
        mx = fmaxf(mx, __shfl_xor_sync(0xffffffffu, mx, off));

    float sum = 0.f;
    for (int j = lane; j < cnt; j += 32) {
        float p = __expf(sc[w][j] - mx);
        sc[w][j] = p;
        sum += p;
    }
#pragma unroll
    for (int off = 16; off > 0; off >>= 1)
        sum += __shfl_xor_sync(0xffffffffu, sum, off);
    const float inv = 1.f / sum;
    __syncwarp();

    // ---- out = sum_m p_m * V[m]; 8 neighbors per iteration, 2 accumulators --
    float4 acc0 = make_float4(0.f, 0.f, 0.f, 0.f);
    float4 acc1 = make_float4(0.f, 0.f, 0.f, 0.f);
    for (int j = 0; j < cnt; j += 8) {
        const int j0 = j + g, j1 = j + 4 + g;
        const bool ok0 = (j0 < cnt), ok1 = (j1 < cnt);
        const int m0 = m_list[ok0 ? j0 : 0];
        const int m1 = m_list[ok1 ? j1 : 0];
        const float p0 = ok0 ? sc[w][j0] : 0.f;
        const float p1 = ok1 ? sc[w][j1] : 0.f;
        const float4 v0 = *(const float4*)(Vh + (size_t)m0 * DHn + sub * 4);
        const float4 v1 = *(const float4*)(Vh + (size_t)m1 * DHn + sub * 4);
        acc0.x = fmaf(p0, v0.x, acc0.x);
        acc0.y = fmaf(p0, v0.y, acc0.y);
        acc0.z = fmaf(p0, v0.z, acc0.z);
        acc0.w = fmaf(p0, v0.w, acc0.w);
        acc1.x = fmaf(p1, v1.x, acc1.x);
        acc1.y = fmaf(p1, v1.y, acc1.y);
        acc1.z = fmaf(p1, v1.z, acc1.z);
        acc1.w = fmaf(p1, v1.w, acc1.w);
    }
    float4 acc = make_float4(acc0.x + acc1.x, acc0.y + acc1.y,
                             acc0.z + acc1.z, acc0.w + acc1.w);
    // combine the 4 neighbor-groups (lanes differing in bits 3,4)
#pragma unroll
    for (int off = 8; off <= 16; off <<= 1) {
        acc.x += __shfl_xor_sync(0xffffffffu, acc.x, off);
        acc.y += __shfl_xor_sync(0xffffffffu, acc.y, off);
        acc.z += __shfl_xor_sync(0xffffffffu, acc.z, off);
        acc.w += __shfl_xor_sync(0xffffffffu, acc.w, off);
    }
    if (g == 0) {
        float4 o = make_float4(acc.x * inv, acc.y * inv, acc.z * inv, acc.w * inv);
        *(float4*)(Ob + (size_t)(b * Ln + n) * En + w * DHn + sub * 4) = o;
    }
}

// ---------------- launch ----------------------------------------------------
extern "C" void kernel_launch(void* const* d_in, const int* in_sizes, int n_in,
                              void* d_out, int out_size)
{
    const float* nf  = (const float*)d_in[0];
    const void*  adj = d_in[1];
    const float* eg  = (const float*)d_in[2];
    const float* Wq = (const float*)d_in[3];
    const float* bq = (const float*)d_in[4];
    const float* Wk = (const float*)d_in[5];
    const float* bk = (const float*)d_in[6];
    const float* Wv = (const float*)d_in[7];
    const float* bv = (const float*)d_in[8];
    const float* Wo = (const float*)d_in[9];
    const float* bo = (const float*)d_in[10];
    float* out = (float*)d_out;

    float *at;
    cudaGetSymbolAddress((void**)&at, g_attn);

    detect_adj_kernel<<<1, 1024>>>((const unsigned char*)adj);

    dim3 qkv_grid(12, (Bn * Ln) / 64);   // (12, 64) = 768 CTAs
    qkv_gemm_kernel<<<qkv_grid, 256>>>(nf, Wq, bq, Wk, bk, Wv, bv);

    dim3 agrid(Ln, Bn);                  // (1024, 4)
    attn_kernel<<<agrid, 256>>>(adj, eg, at);

    dim3 ogrid(En / 64, (Bn * Ln) / 64); // (4, 64) = 256 CTAs
    out_gemm_kernel<<<ogrid, 256>>>(at, Wo, bo, out);
}

// round 12
// speedup vs baseline: 2.1867x; 1.0198x over previous
#include <cuda_runtime.h>
#include <cuda_bf16.h>
#include <cstddef>

// Problem constants
#define Bn  4
#define Ln  1024
#define En  256
#define Hn  8
#define DHn 32
#define LDST 68   // smem row stride (floats): 16B-aligned, conflict-mitigating

// ---------------- scratch (device globals; no allocation allowed) -----------
__device__ float g_q[Bn * Ln * En];        // Q pre-scaled by 1/16, [b][n][h*32+d]
__device__ float g_k[Bn * Hn * Ln * DHn];  // K head-major [b][h][m][d]
__device__ float g_v[Bn * Hn * Ln * DHn];  // V head-major [b][h][m][d]
__device__ float g_attn[Bn * Ln * En];     // attention output [b][n][h*32+d]
__device__ int   g_adj_is_byte;            // 1 = adjacency stored as 1-byte elems

// ---------------- adjacency dtype detection (parallel) -----------------------
__global__ void __launch_bounds__(1024)
detect_adj_kernel(const unsigned char* __restrict__ adj)
{
    __shared__ int ok;
    if (threadIdx.x == 0) ok = 1;
    __syncthreads();
    if (adj[(size_t)threadIdx.x * Ln + threadIdx.x] != 1) ok = 0;  // benign race
    __syncthreads();
    if (threadIdx.x == 0) g_adj_is_byte = ok;
}

// ---------------- shared 64x64 SGEMM mainloop (double-buffered) --------------
// acc[4][4] = A[row0+ty*4+i][:] . W[col0+tx*4+j][:]  (K = 256)
// Two smem stages, ONE __syncthreads per 16-wide k-chunk; next chunk's global
// loads issued before the compute block so L2 latency hides behind 256 FMAs.
__device__ __forceinline__ void gemm64_body(const float* __restrict__ A,
                                            const float* __restrict__ W,
                                            int row0, int col0,
                                            float (&acc)[4][4],
                                            float* As, float* Bs)
{
    const int tid  = threadIdx.x;
    const int ty   = tid >> 4, tx = tid & 15;
    const int lrow = tid >> 2, lks = (tid & 3) * 4;

    const float* Ap = A + (size_t)(row0 + lrow) * 256 + lks;
    const float* Wp = W + (size_t)(col0 + lrow) * 256 + lks;

    // preload chunk 0 into stage 0
    {
        float4 a4 = *(const float4*)(Ap);
        float4 b4 = *(const float4*)(Wp);
        As[(lks + 0) * LDST + lrow] = a4.x;
        As[(lks + 1) * LDST + lrow] = a4.y;
        As[(lks + 2) * LDST + lrow] = a4.z;
        As[(lks + 3) * LDST + lrow] = a4.w;
        Bs[(lks + 0) * LDST + lrow] = b4.x;
        Bs[(lks + 1) * LDST + lrow] = b4.y;
        Bs[(lks + 2) * LDST + lrow] = b4.z;
        Bs[(lks + 3) * LDST + lrow] = b4.w;
    }
    __syncthreads();

#pragma unroll 1
    for (int it = 0; it < 16; it++) {
        float* Ac = As + (it & 1) * (16 * LDST);
        float* Bc = Bs + (it & 1) * (16 * LDST);
        float* An = As + ((it & 1) ^ 1) * (16 * LDST);
        float* Bn_ = Bs + ((it & 1) ^ 1) * (16 * LDST);

        float4 a4, b4;
        const bool more = (it < 15);
        if (more) {
            a4 = *(const float4*)(Ap + (it + 1) * 16);   // issued early;
            b4 = *(const float4*)(Wp + (it + 1) * 16);   // consumed after FMAs
        }
#pragma unroll
        for (int k = 0; k < 16; k++) {
            float4 av = *(const float4*)&Ac[k * LDST + ty * 4];
            float4 bv = *(const float4*)&Bc[k * LDST + tx * 4];
            acc[0][0] = fmaf(av.x, bv.x, acc[0][0]);
            acc[0][1] = fmaf(av.x, bv.y, acc[0][1]);
            acc[0][2] = fmaf(av.x, bv.z, acc[0][2]);
            acc[0][3] = fmaf(av.x, bv.w, acc[0][3]);
            acc[1][0] = fmaf(av.y, bv.x, acc[1][0]);
            acc[1][1] = fmaf(av.y, bv.y, acc[1][1]);
            acc[1][2] = fmaf(av.y, bv.z, acc[1][2]);
            acc[1][3] = fmaf(av.y, bv.w, acc[1][3]);
            acc[2][0] = fmaf(av.z, bv.x, acc[2][0]);
            acc[2][1] = fmaf(av.z, bv.y, acc[2][1]);
            acc[2][2] = fmaf(av.z, bv.z, acc[2][2]);
            acc[2][3] = fmaf(av.z, bv.w, acc[2][3]);
            acc[3][0] = fmaf(av.w, bv.x, acc[3][0]);
            acc[3][1] = fmaf(av.w, bv.y, acc[3][1]);
            acc[3][2] = fmaf(av.w, bv.z, acc[3][2]);
            acc[3][3] = fmaf(av.w, bv.w, acc[3][3]);
        }
        if (more) {
            // stage it^1 was last READ in iteration it-1; the sync at the end
            // of that iteration protects this store.
            An [(lks + 0) * LDST + lrow] = a4.x;
            An [(lks + 1) * LDST + lrow] = a4.y;
            An [(lks + 2) * LDST + lrow] = a4.z;
            An [(lks + 3) * LDST + lrow] = a4.w;
            Bn_[(lks + 0) * LDST + lrow] = b4.x;
            Bn_[(lks + 1) * LDST + lrow] = b4.y;
            Bn_[(lks + 2) * LDST + lrow] = b4.z;
            Bn_[(lks + 3) * LDST + lrow] = b4.w;
            __syncthreads();
        }
    }
}

// ---------------- fused QKV projection ---------------------------------------
__global__ void __launch_bounds__(256)
qkv_gemm_kernel(const float* __restrict__ A,
                const float* __restrict__ Wq, const float* __restrict__ bq,
                const float* __restrict__ Wk, const float* __restrict__ bk,
                const float* __restrict__ Wv, const float* __restrict__ bv)
{
    __shared__ __align__(16) float As[2 * 16 * LDST];
    __shared__ __align__(16) float Bs[2 * 16 * LDST];

    const int wsel = blockIdx.x >> 2;            // 0=Q 1=K 2=V
    const int col0 = (blockIdx.x & 3) * 64;
    const int row0 = blockIdx.y * 64;

    const float* W    = (wsel == 0) ? Wq : (wsel == 1) ? Wk : Wv;
    const float* bias = (wsel == 0) ? bq : (wsel == 1) ? bk : bv;

    float acc[4][4];
#pragma unroll
    for (int i = 0; i < 4; i++)
#pragma unroll
        for (int j = 0; j < 4; j++) acc[i][j] = 0.f;

    gemm64_body(A, W, row0, col0, acc, As, Bs);

    const int ty = threadIdx.x >> 4, tx = threadIdx.x & 15;
#pragma unroll
    for (int i = 0; i < 4; i++) {
        int r = row0 + ty * 4 + i;
#pragma unroll
        for (int j = 0; j < 4; j++) {
            int c = col0 + tx * 4 + j;
            float v = acc[i][j] + bias[c];
            if (wsel == 0) {
                g_q[(size_t)r * 256 + c] = v * 0.0625f;  // pre-scale 1/sqrt(256)
            } else {
                int idx = (((r >> 10) * Hn + (c >> 5)) * Ln + (r & 1023)) * DHn + (c & 31);
                if (wsel == 1) g_k[idx] = v; else g_v[idx] = v;
            }
        }
    }
}

// ---------------- output projection ------------------------------------------
__global__ void __launch_bounds__(256)
out_gemm_kernel(const float* __restrict__ A, const float* __restrict__ W,
                const float* __restrict__ bias, float* __restrict__ C)
{
    __shared__ __align__(16) float As[2 * 16 * LDST];
    __shared__ __align__(16) float Bs[2 * 16 * LDST];

    const int col0 = blockIdx.x * 64;
    const int row0 = blockIdx.y * 64;

    float acc[4][4];
#pragma unroll
    for (int i = 0; i < 4; i++)
#pragma unroll
        for (int j = 0; j < 4; j++) acc[i][j] = 0.f;

    gemm64_body(A, W, row0, col0, acc, As, Bs);

    const int ty = threadIdx.x >> 4, tx = threadIdx.x & 15;
#pragma unroll
    for (int i = 0; i < 4; i++) {
        int r = row0 + ty * 4 + i;
#pragma unroll
        for (int j = 0; j < 4; j++) {
            int c = col0 + tx * 4 + j;
            C[(size_t)r * 256 + c] = acc[i][j] + bias[c];
        }
    }
}

// ---------------- fused sparse attention (unchanged from R11) ----------------
__global__ void __launch_bounds__(256)
attn_kernel(const void* __restrict__ AdjRaw, const float* __restrict__ Eg,
            float* __restrict__ Ob)
{
    __shared__ float q_s[En];
    __shared__ int   m_list[Ln];
    __shared__ float sc[Hn][Ln];
    __shared__ int   m_cnt;

    const int n    = blockIdx.x;
    const int b    = blockIdx.y;
    const int tid  = threadIdx.x;
    const int w    = tid >> 5;
    const int lane = tid & 31;
    const int g    = lane >> 3;
    const int sub  = lane & 7;
    const int isbyte = g_adj_is_byte;

    q_s[tid] = g_q[(size_t)(b * Ln + n) * En + tid];
    if (tid == 0) m_cnt = 0;
    __syncthreads();

    const unsigned char* arow8  = (const unsigned char*)AdjRaw + (size_t)(b * Ln + n) * Ln;
    const unsigned int*  arow32 = (const unsigned int*) AdjRaw + (size_t)(b * Ln + n) * Ln;
#pragma unroll
    for (int base = 0; base < Ln; base += 256) {
        int m = base + tid;
        bool valid = isbyte ? (arow8[m] != 0) : (arow32[m] != 0u);
        unsigned bal = __ballot_sync(0xffffffffu, valid);
        int pos = 0;
        if (lane == 0 && bal) pos = atomicAdd(&m_cnt, __popc(bal));
        pos = __shfl_sync(0xffffffffu, pos, 0);
        if (valid) m_list[pos + __popc(bal & ((1u << lane) - 1))] = m;
    }
    __syncthreads();
    const int cnt = m_cnt;

    const float* Kh   = g_k + (size_t)(b * Hn + w) * Ln * DHn;
    const float* Vh   = g_v + (size_t)(b * Hn + w) * Ln * DHn;
    const float* Erow = Eg + (size_t)(b * Ln + n) * Ln * DHn;

    const float4 q4 = *(const float4*)&q_s[w * DHn + sub * 4];

    for (int i = 0; i < cnt; i += 8) {
        const int j0 = i + g, j1 = i + 4 + g;
        const int m0 = m_list[(j0 < cnt) ? j0 : 0];
        const int m1 = m_list[(j1 < cnt) ? j1 : 0];
        const float4 k0 = *(const float4*)(Kh   + (size_t)m0 * DHn + sub * 4);
        const float4 e0 = *(const float4*)(Erow + (size_t)m0 * DHn + sub * 4);
        const float4 k1 = *(const float4*)(Kh   + (size_t)m1 * DHn + sub * 4);
        const float4 e1 = *(const float4*)(Erow + (size_t)m1 * DHn + sub * 4);
        float s0, s1;
        s0 = q4.x * (k0.x + e0.x);
        s1 = q4.x * (k1.x + e1.x);
        s0 = fmaf(q4.y, k0.y + e0.y, s0);
        s1 = fmaf(q4.y, k1.y + e1.y, s1);
        s0 = fmaf(q4.z, k0.z + e0.z, s0);
        s1 = fmaf(q4.z, k1.z + e1.z, s1);
        s0 = fmaf(q4.w, k0.w + e0.w, s0);
        s1 = fmaf(q4.w, k1.w + e1.w, s1);
        s0 += __shfl_xor_sync(0xffffffffu, s0, 1);
        s1 += __shfl_xor_sync(0xffffffffu, s1, 1);
        s0 += __shfl_xor_sync(0xffffffffu, s0, 2);
        s1 += __shfl_xor_sync(0xffffffffu, s1, 2);
        s0 += __shfl_xor_sync(0xffffffffu, s0, 4);
        s1 += __shfl_xor_sync(0xffffffffu, s1, 4);
        if (sub == 0) {
            if (j0 < cnt) sc[w][j0] = s0;
            if (j1 < cnt) sc[w][j1] = s1;
        }
    }
    __syncwarp();

    float mx = -1e30f;
    for (int j = lane; j < cnt; j += 32) mx = fmaxf(mx, sc[w][j]);
#pragma unroll
    for (int off = 16; off > 0; off >>= 1)
        mx = fmaxf(mx, __shfl_xor_sync(0xffffffffu, mx, off));

    float sum = 0.f;
    for (int j = lane; j < cnt; j += 32) {
        float p = __expf(sc[w][j] - mx);
        sc[w][j] = p;
        sum += p;
    }
#pragma unroll
    for (int off = 16; off > 0; off >>= 1)
        sum += __shfl_xor_sync(0xffffffffu, sum, off);
    const float inv = 1.f / sum;
    __syncwarp();

    float4 acc0 = make_float4(0.f, 0.f, 0.f, 0.f);
    float4 acc1 = make_float4(0.f, 0.f, 0.f, 0.f);
    for (int j = 0; j < cnt; j += 8) {
        const int j0 = j + g, j1 = j + 4 + g;
        const bool ok0 = (j0 < cnt), ok1 = (j1 < cnt);
        const int m0 = m_list[ok0 ? j0 : 0];
        const int m1 = m_list[ok1 ? j1 : 0];
        const float p0 = ok0 ? sc[w][j0] : 0.f;
        const float p1 = ok1 ? sc[w][j1] : 0.f;
        const float4 v0 = *(const float4*)(Vh + (size_t)m0 * DHn + sub * 4);
        const float4 v1 = *(const float4*)(Vh + (size_t)m1 * DHn + sub * 4);
        acc0.x = fmaf(p0, v0.x, acc0.x);
        acc0.y = fmaf(p0, v0.y, acc0.y);
        acc0.z = fmaf(p0, v0.z, acc0.z);
        acc0.w = fmaf(p0, v0.w, acc0.w);
        acc1.x = fmaf(p1, v1.x, acc1.x);
        acc1.y = fmaf(p1, v1.y, acc1.y);
        acc1.z = fmaf(p1, v1.z, acc1.z);
        acc1.w = fmaf(p1, v1.w, acc1.w);
    }
    float4 acc = make_float4(acc0.x + acc1.x, acc0.y + acc1.y,
                             acc0.z + acc1.z, acc0.w + acc1.w);
#pragma unroll
    for (int off = 8; off <= 16; off <<= 1) {
        acc.x += __shfl_xor_sync(0xffffffffu, acc.x, off);
        acc.y += __shfl_xor_sync(0xffffffffu, acc.y, off);
        acc.z += __shfl_xor_sync(0xffffffffu, acc.z, off);
        acc.w += __shfl_xor_sync(0xffffffffu, acc.w, off);
    }
    if (g == 0) {
        float4 o = make_float4(acc.x * inv, acc.y * inv, acc.z * inv, acc.w * inv);
        *(float4*)(Ob + (size_t)(b * Ln + n) * En + w * DHn + sub * 4) = o;
    }
}

// ---------------- launch ----------------------------------------------------
extern "C" void kernel_launch(void* const* d_in, const int* in_sizes, int n_in,
                              void* d_out, int out_size)
{
    const float* nf  = (const float*)d_in[0];
    const void*  adj = d_in[1];
    const float* eg  = (const float*)d_in[2];
    const float* Wq = (const float*)d_in[3];
    const float* bq = (const float*)d_in[4];
    const float* Wk = (const float*)d_in[5];
    const float* bk = (const float*)d_in[6];
    const float* Wv = (const float*)d_in[7];
    const float* bv = (const float*)d_in[8];
    const float* Wo = (const float*)d_in[9];
    const float* bo = (const float*)d_in[10];
    float* out = (float*)d_out;

    float *at;
    cudaGetSymbolAddress((void**)&at, g_attn);

    detect_adj_kernel<<<1, 1024>>>((const unsigned char*)adj);

    dim3 qkv_grid(12, (Bn * Ln) / 64);   // 768 CTAs
    qkv_gemm_kernel<<<qkv_grid, 256>>>(nf, Wq, bq, Wk, bk, Wv, bv);

    dim3 agrid(Ln, Bn);                  // 4096 CTAs
    attn_kernel<<<agrid, 256>>>(adj, eg, at);

    dim3 ogrid(En / 64, (Bn * Ln) / 64); // 256 CTAs
    out_gemm_kernel<<<ogrid, 256>>>(at, Wo, bo, out);
}